// round 15
// baseline (speedup 1.0000x reference)
#include <cuda_runtime.h>
#include <cuda_bf16.h>
#include <math.h>
#include <stdint.h>

#define BB 1024
#define QQ 32
#define DD 512
#define NJQ (BB * QQ)
#define NUM_HARD 512

#define CTA_M 128
#define CTA_N 128
#define CKH   64                         // K halves per chunk (128 B/row)
#define NCHUNK (DD / CKH)                // 8
#define A_BYTES (CTA_M * CKH * 2)        // 16384
#define B_BYTES (CTA_N * CKH * 2)        // 16384
#define STAGE_BYTES (A_BYTES + B_BYTES)  // 32768
#define NSTAGE 3
#define SMEM_BYTES (NSTAGE * STAGE_BYTES) // 98304 -> 2 CTAs/SM
#define NTHR 128                          // 4 warps of 64x64

#define FN4 (BB * DD / 4)
#define TN4 (NJQ * DD / 4)

__device__ float g_simmax[BB * BB];
__device__ float g_rowloss[BB];
__device__ unsigned g_done;
__device__ uint4 g_fusion_h[BB * DD / 8];
__device__ uint4 g_target_h[NJQ * DD / 8];

// ---------------------------------------------------------------------------
// fp32 -> bf16 (RNE): 4 uint4 outputs (8 float4 loads) per thread-iteration
// for MLP; FN4/2 = 65536 divisible by 4, so a 4-group never straddles regions.
// ---------------------------------------------------------------------------
__device__ __forceinline__ unsigned pack_bf16(float x, float y)
{
    __nv_bfloat162 h = __float22bfloat162_rn(make_float2(x, y));
    return *(unsigned*)&h;
}

__global__ __launch_bounds__(256) void cvt_bf16_kernel(
    const float4* __restrict__ fus, const float4* __restrict__ tgt)
{
    if (blockIdx.x == 0 && threadIdx.x == 0) g_done = 0;
    const int nfo = FN4 / 2;                 // fusion uint4 outputs (65536)
    const int nto = TN4 / 2;                 // target uint4 outputs
    const int nquads = (nfo + nto) / 4;      // groups of 4 uint4 outputs
    for (int qd = blockIdx.x * blockDim.x + threadIdx.x; qd < nquads;
         qd += gridDim.x * blockDim.x) {
        const int o0 = qd * 4;               // first uint4 output index
        const float4* src;
        uint4* dst;
        if (o0 < nfo) { src = fus + 2 * (size_t)o0;        dst = g_fusion_h + o0; }
        else { int k = o0 - nfo; src = tgt + 2 * (size_t)k; dst = g_target_h + k; }
        float4 v[8];
#pragma unroll
        for (int r = 0; r < 8; r++) v[r] = src[r];
#pragma unroll
        for (int u = 0; u < 4; u++) {
            uint4 o;
            o.x = pack_bf16(v[2 * u].x, v[2 * u].y);
            o.y = pack_bf16(v[2 * u].z, v[2 * u].w);
            o.z = pack_bf16(v[2 * u + 1].x, v[2 * u + 1].y);
            o.w = pack_bf16(v[2 * u + 1].z, v[2 * u + 1].w);
            dst[u] = o;
        }
    }
}

// ---------------------------------------------------------------------------
// bf16 tensor-core GEMM + max-over-q epilogue (mma.m16n8k16, fp32 accum).
// CTA 128x128, 4 warps (2x2) of 64x64; 2 CTAs/SM; chunk loop FULLY UNROLLED
// so stage/k offsets fold to immediates (no per-chunk address ALU).
// ---------------------------------------------------------------------------
__device__ __forceinline__ void mma_bf16(float c[4], unsigned a0, unsigned a1,
                                         unsigned a2, unsigned a3,
                                         unsigned b0, unsigned b1)
{
    asm volatile(
        "mma.sync.aligned.m16n8k16.row.col.f32.bf16.bf16.f32 "
        "{%0,%1,%2,%3},{%4,%5,%6,%7},{%8,%9},{%0,%1,%2,%3};"
        : "+f"(c[0]), "+f"(c[1]), "+f"(c[2]), "+f"(c[3])
        : "r"(a0), "r"(a1), "r"(a2), "r"(a3), "r"(b0), "r"(b1));
}

#define LDSM4(r0, r1, r2, r3, addr) \
    asm volatile("ldmatrix.sync.aligned.m8n8.x4.shared.b16 {%0,%1,%2,%3}, [%4];" \
                 : "=r"(r0), "=r"(r1), "=r"(r2), "=r"(r3) : "r"(addr))

__device__ __forceinline__ void cp16(unsigned saddr, const void* gaddr)
{
    asm volatile("cp.async.cg.shared.global [%0], [%1], 16;"
                 :: "r"(saddr), "l"(gaddr));
}

__global__ __launch_bounds__(NTHR, 2) void sim_tc(const float* __restrict__ temp_p)
{
    extern __shared__ float sm[];
    const int t    = threadIdx.x;
    const int wid  = t >> 5;
    const int lane = t & 31;
    const int g    = lane >> 2;
    const int tg   = lane & 3;
    const int wm   = (wid >> 1) * 64;
    const int wn   = (wid & 1) * 64;
    const int i0   = blockIdx.x * CTA_M;
    const int jq0  = blockIdx.y * CTA_N;

    float c[4][8][4];
#pragma unroll
    for (int mf = 0; mf < 4; mf++)
#pragma unroll
        for (int nf = 0; nf < 8; nf++)
#pragma unroll
            for (int r = 0; r < 4; r++) c[mf][nf][r] = 0.f;

    const unsigned sbase = (unsigned)__cvta_generic_to_shared(sm);
    const __nv_bfloat16* fus = (const __nv_bfloat16*)g_fusion_h;
    const __nv_bfloat16* tgt = (const __nv_bfloat16*)g_target_h;

    const __nv_bfloat16* agp[8]; unsigned aso[8];
#pragma unroll
    for (int p = 0; p < 8; p++) {
        int idx4 = t + p * NTHR;
        int row = idx4 >> 3, kb = idx4 & 7;
        agp[p] = fus + (size_t)(i0 + row) * DD + kb * 8;
        aso[p] = (unsigned)(row * 128 + ((kb ^ (row & 7)) << 4));
    }
    const __nv_bfloat16* bgp[8]; unsigned bso[8];
#pragma unroll
    for (int p = 0; p < 8; p++) {
        int idx4 = t + p * NTHR;
        int row = idx4 >> 3, kb = idx4 & 7;
        bgp[p] = tgt + (size_t)(jq0 + row) * DD + kb * 8;
        bso[p] = (unsigned)(A_BYTES + row * 128 + ((kb ^ (row & 7)) << 4));
    }

    unsigned a_byte[4]; int a_r7[4];
    const int a_csel = lane >> 4;
#pragma unroll
    for (int mf = 0; mf < 4; mf++) {
        int row = wm + (mf << 4) + (((lane >> 3) & 1) << 3) + (lane & 7);
        a_byte[mf] = (unsigned)(row * 128);
        a_r7[mf] = row & 7;
    }
    unsigned b_byte[4]; int b_r7[4];
    const int b_csel = (lane >> 3) & 1;
#pragma unroll
    for (int p = 0; p < 4; p++) {
        int row = wn + (p << 4) + ((lane >> 4) << 3) + (lane & 7);
        b_byte[p] = (unsigned)(A_BYTES + row * 128);
        b_r7[p] = row & 7;
    }

    // prologue: stage chunks 0, 1
#pragma unroll
    for (int pc = 0; pc < 2; pc++) {
        unsigned sb = sbase + pc * STAGE_BYTES;
#pragma unroll
        for (int p = 0; p < 8; p++) cp16(sb + aso[p], agp[p] + pc * CKH);
#pragma unroll
        for (int p = 0; p < 8; p++) cp16(sb + bso[p], bgp[p] + pc * CKH);
        asm volatile("cp.async.commit_group;" ::: "memory");
    }

#pragma unroll
    for (int ch = 0; ch < NCHUNK; ch++) {
        if (ch == NCHUNK - 1)
            asm volatile("cp.async.wait_group 0;" ::: "memory");
        else
            asm volatile("cp.async.wait_group 1;" ::: "memory");
        __syncthreads();

        if (ch + 2 < NCHUNK) {
            const int k0 = (ch + 2) * CKH;
            unsigned sb = sbase + (unsigned)(((ch + 2) % NSTAGE) * STAGE_BYTES);
#pragma unroll
            for (int p = 0; p < 8; p++) cp16(sb + aso[p], agp[p] + k0);
#pragma unroll
            for (int p = 0; p < 8; p++) cp16(sb + bso[p], bgp[p] + k0);
            asm volatile("cp.async.commit_group;" ::: "memory");
        }

        const unsigned stg = sbase + (unsigned)((ch % NSTAGE) * STAGE_BYTES);

#pragma unroll
        for (int s = 0; s < 4; s++) {
            unsigned a[4][4];
#pragma unroll
            for (int mf = 0; mf < 4; mf++) {
                unsigned ad = stg + a_byte[mf]
                    + (unsigned)(((((s << 1) | a_csel) ^ a_r7[mf])) << 4);
                LDSM4(a[mf][0], a[mf][1], a[mf][2], a[mf][3], ad);
            }
            unsigned b[8][2];
#pragma unroll
            for (int p = 0; p < 4; p++) {
                unsigned bd = stg + b_byte[p]
                    + (unsigned)(((((s << 1) | b_csel) ^ b_r7[p])) << 4);
                LDSM4(b[2 * p][0], b[2 * p][1], b[2 * p + 1][0], b[2 * p + 1][1], bd);
            }
#pragma unroll
            for (int nf = 0; nf < 8; nf++)
#pragma unroll
                for (int mf = 0; mf < 4; mf++)
                    mma_bf16(c[mf][nf], a[mf][0], a[mf][1], a[mf][2], a[mf][3],
                             b[nf][0], b[nf][1]);
        }
    }

    // epilogue: warp covers 64 N-cols = two j's
    const float invt = 1.0f / temp_p[0];
#pragma unroll
    for (int mf = 0; mf < 4; mf++) {
#pragma unroll
        for (int h = 0; h < 2; h++) {
#pragma unroll
            for (int jh = 0; jh < 2; jh++) {
                float v = -INFINITY;
#pragma unroll
                for (int nf = 4 * jh; nf < 4 * jh + 4; nf++)
                    v = fmaxf(v, fmaxf(c[mf][nf][2 * h], c[mf][nf][2 * h + 1]));
                v = fmaxf(v, __shfl_xor_sync(0xffffffffu, v, 1));
                v = fmaxf(v, __shfl_xor_sync(0xffffffffu, v, 2));
                if (tg == 0) {
                    int row = i0 + wm + (mf << 4) + (h << 3) + g;
                    int j   = ((jq0 + wn) >> 5) + jh;
                    g_simmax[(size_t)row * BB + j] = v * invt;
                }
            }
        }
    }
}

// ---------------------------------------------------------------------------
// Per-row loss: one warp per row; exact top-512 via 32-step binary search.
// Last finished block reduces g_rowloss to the scalar (deterministic order).
// ---------------------------------------------------------------------------
__device__ __forceinline__ unsigned f2key(float f)
{
    unsigned b = __float_as_uint(f);
    return (b & 0x80000000u) ? ~b : (b | 0x80000000u);
}
__device__ __forceinline__ float key2f(unsigned k)
{
    return __uint_as_float((k & 0x80000000u) ? (k ^ 0x80000000u) : ~k);
}

__global__ __launch_bounds__(128) void loss_warp(float* __restrict__ out)
{
    __shared__ float red[128];
    __shared__ bool s_last;

    const int lane = threadIdx.x & 31;
    const int i = (blockIdx.x << 2) + (threadIdx.x >> 5);
    const float* rowp = g_simmax + (size_t)i * BB;

    float v[32];
    float m = -INFINITY, posl = 0.f;
#pragma unroll
    for (int r = 0; r < 32; r++) {
        v[r] = rowp[(r << 5) + lane];
        m = fmaxf(m, v[r]);
        if ((r << 5) + lane == i) posl = v[r];
    }
#pragma unroll
    for (int s = 16; s >= 1; s >>= 1)
        m = fmaxf(m, __shfl_xor_sync(0xffffffffu, m, s));
    float pos = posl;
#pragma unroll
    for (int s = 16; s >= 1; s >>= 1)
        pos += __shfl_xor_sync(0xffffffffu, pos, s);

    float ev[32]; unsigned key[32];
    float sum = 0.f;
#pragma unroll
    for (int r = 0; r < 32; r++) {
        ev[r] = expf(v[r] - m);
        sum += ev[r];
        key[r] = ((r << 5) + lane == i) ? 0u : f2key(v[r]);
    }
#pragma unroll
    for (int s = 16; s >= 1; s >>= 1)
        sum += __shfl_xor_sync(0xffffffffu, sum, s);
    const float lse_all = logf(sum) + m;

    unsigned lo = 0u, hi = 0xFFFFFFFFu;
    for (int it = 0; it < 32; it++) {
        unsigned mid = lo + ((hi - lo) >> 1);
        unsigned cl = 0;
#pragma unroll
        for (int r = 0; r < 32; r++) cl += (key[r] > mid);
        unsigned cnt = __reduce_add_sync(0xffffffffu, cl);
        if (cnt >= NUM_HARD) lo = mid; else hi = mid;
    }

    unsigned cgl = 0; float hsum = 0.f;
#pragma unroll
    for (int r = 0; r < 32; r++) {
        if (key[r] > hi) { cgl++; hsum += ev[r]; }
    }
    unsigned cgt = __reduce_add_sync(0xffffffffu, cgl);
#pragma unroll
    for (int s = 16; s >= 1; s >>= 1)
        hsum += __shfl_xor_sync(0xffffffffu, hsum, s);
    hsum += (float)(NUM_HARD - cgt) * expf(key2f(hi) - m) + expf(pos - m);

    if (lane == 0) {
        const float lse_h = logf(hsum) + m;
        g_rowloss[i] = (lse_all - pos) + 0.5f * (lse_h - pos);
    }

    __syncthreads();
    if (threadIdx.x == 0) {
        __threadfence();
        unsigned prev = atomicAdd(&g_done, 1u);
        s_last = (prev == (BB / 4) - 1);
    }
    __syncthreads();
    if (s_last) {
        const int t = threadIdx.x;
        float s = 0.f;
#pragma unroll
        for (int p = 0; p < 8; p++) s += g_rowloss[t + p * 128];
        red[t] = s;
        __syncthreads();
        for (int st = 64; st > 0; st >>= 1) {
            if (t < st) red[t] += red[t + st];
            __syncthreads();
        }
        if (t == 0) out[0] = red[0] / (float)BB;
    }
}

extern "C" void kernel_launch(void* const* d_in, const int* in_sizes, int n_in,
                              void* d_out, int out_size)
{
    const float* fusion = (const float*)d_in[0];
    const float* target = (const float*)d_in[1];
    const float* temp   = (const float*)d_in[2];
    float* out = (float*)d_out;

    cudaFuncSetAttribute(sim_tc, cudaFuncAttributeMaxDynamicSharedMemorySize,
                         SMEM_BYTES);

    cvt_bf16_kernel<<<2048, 256>>>((const float4*)fusion, (const float4*)target);

    dim3 grid(BB / CTA_M, NJQ / CTA_N);   // (8, 256)
    sim_tc<<<grid, NTHR, SMEM_BYTES>>>(temp);

    loss_warp<<<BB / 4, 128>>>(out);
}

// round 16
// speedup vs baseline: 1.0799x; 1.0799x over previous
#include <cuda_runtime.h>
#include <cuda_bf16.h>
#include <math.h>
#include <stdint.h>

#define BB 1024
#define QQ 32
#define DD 512
#define NJQ (BB * QQ)
#define NUM_HARD 512

#define CTA_M 128
#define CTA_N 128
#define CKH   64                         // K halves per chunk (128 B/row)
#define NCHUNK (DD / CKH)                // 8
#define A_BYTES (CTA_M * CKH * 2)        // 16384
#define B_BYTES (CTA_N * CKH * 2)        // 16384
#define STAGE_BYTES (A_BYTES + B_BYTES)  // 32768
#define NSTAGE 3
#define SMEM_BYTES (NSTAGE * STAGE_BYTES) // 98304 -> 2 CTAs/SM
#define NTHR 128                          // 4 warps of 64x64

#define FN4 (BB * DD / 4)
#define TN4 (NJQ * DD / 4)

__device__ float g_simmax[BB * BB];
__device__ float g_rowloss[BB];
__device__ unsigned g_done;
__device__ uint4 g_fusion_h[BB * DD / 8];
__device__ uint4 g_target_h[NJQ * DD / 8];

// ---------------------------------------------------------------------------
// fp32 -> bf16 (RNE): 2 consecutive float4 in, 1 uint4 out per thread-iter
// (coalesced 32B/thread contiguous across the warp — the R13/R14 measured-good
// version; the R15 4-wide variant broke coalescing and regressed).
// ---------------------------------------------------------------------------
__device__ __forceinline__ unsigned pack_bf16(float x, float y)
{
    __nv_bfloat162 h = __float22bfloat162_rn(make_float2(x, y));
    return *(unsigned*)&h;
}

__global__ __launch_bounds__(256) void cvt_bf16_kernel(
    const float4* __restrict__ fus, const float4* __restrict__ tgt)
{
    if (blockIdx.x == 0 && threadIdx.x == 0) g_done = 0;
    const int nfo = FN4 / 2;
    const int nto = TN4 / 2;
    for (int i = blockIdx.x * blockDim.x + threadIdx.x; i < nfo + nto;
         i += gridDim.x * blockDim.x) {
        const float4* src;
        uint4* dst;
        if (i < nfo) { src = fus + 2 * (size_t)i;          dst = g_fusion_h + i; }
        else { int k = i - nfo; src = tgt + 2 * (size_t)k; dst = g_target_h + k; }
        float4 v0 = src[0];
        float4 v1 = src[1];
        uint4 o;
        o.x = pack_bf16(v0.x, v0.y);
        o.y = pack_bf16(v0.z, v0.w);
        o.z = pack_bf16(v1.x, v1.y);
        o.w = pack_bf16(v1.z, v1.w);
        *dst = o;
    }
}

// ---------------------------------------------------------------------------
// bf16 tensor-core GEMM + max-over-q epilogue (mma.m16n8k16, fp32 accum).
// CTA 128x128, 4 warps (2x2) of 64x64; 2 CTAs/SM; chunk loop fully unrolled
// (stage/k offsets fold to immediates — measured ~9.5us win in R15).
// ---------------------------------------------------------------------------
__device__ __forceinline__ void mma_bf16(float c[4], unsigned a0, unsigned a1,
                                         unsigned a2, unsigned a3,
                                         unsigned b0, unsigned b1)
{
    asm volatile(
        "mma.sync.aligned.m16n8k16.row.col.f32.bf16.bf16.f32 "
        "{%0,%1,%2,%3},{%4,%5,%6,%7},{%8,%9},{%0,%1,%2,%3};"
        : "+f"(c[0]), "+f"(c[1]), "+f"(c[2]), "+f"(c[3])
        : "r"(a0), "r"(a1), "r"(a2), "r"(a3), "r"(b0), "r"(b1));
}

#define LDSM4(r0, r1, r2, r3, addr) \
    asm volatile("ldmatrix.sync.aligned.m8n8.x4.shared.b16 {%0,%1,%2,%3}, [%4];" \
                 : "=r"(r0), "=r"(r1), "=r"(r2), "=r"(r3) : "r"(addr))

__device__ __forceinline__ void cp16(unsigned saddr, const void* gaddr)
{
    asm volatile("cp.async.cg.shared.global [%0], [%1], 16;"
                 :: "r"(saddr), "l"(gaddr));
}

__global__ __launch_bounds__(NTHR, 2) void sim_tc(const float* __restrict__ temp_p)
{
    extern __shared__ float sm[];
    const int t    = threadIdx.x;
    const int wid  = t >> 5;
    const int lane = t & 31;
    const int g    = lane >> 2;
    const int tg   = lane & 3;
    const int wm   = (wid >> 1) * 64;
    const int wn   = (wid & 1) * 64;
    const int i0   = blockIdx.x * CTA_M;
    const int jq0  = blockIdx.y * CTA_N;

    float c[4][8][4];
#pragma unroll
    for (int mf = 0; mf < 4; mf++)
#pragma unroll
        for (int nf = 0; nf < 8; nf++)
#pragma unroll
            for (int r = 0; r < 4; r++) c[mf][nf][r] = 0.f;

    const unsigned sbase = (unsigned)__cvta_generic_to_shared(sm);
    const __nv_bfloat16* fus = (const __nv_bfloat16*)g_fusion_h;
    const __nv_bfloat16* tgt = (const __nv_bfloat16*)g_target_h;

    const __nv_bfloat16* agp[8]; unsigned aso[8];
#pragma unroll
    for (int p = 0; p < 8; p++) {
        int idx4 = t + p * NTHR;
        int row = idx4 >> 3, kb = idx4 & 7;
        agp[p] = fus + (size_t)(i0 + row) * DD + kb * 8;
        aso[p] = (unsigned)(row * 128 + ((kb ^ (row & 7)) << 4));
    }
    const __nv_bfloat16* bgp[8]; unsigned bso[8];
#pragma unroll
    for (int p = 0; p < 8; p++) {
        int idx4 = t + p * NTHR;
        int row = idx4 >> 3, kb = idx4 & 7;
        bgp[p] = tgt + (size_t)(jq0 + row) * DD + kb * 8;
        bso[p] = (unsigned)(A_BYTES + row * 128 + ((kb ^ (row & 7)) << 4));
    }

    unsigned a_byte[4]; int a_r7[4];
    const int a_csel = lane >> 4;
#pragma unroll
    for (int mf = 0; mf < 4; mf++) {
        int row = wm + (mf << 4) + (((lane >> 3) & 1) << 3) + (lane & 7);
        a_byte[mf] = (unsigned)(row * 128);
        a_r7[mf] = row & 7;
    }
    unsigned b_byte[4]; int b_r7[4];
    const int b_csel = (lane >> 3) & 1;
#pragma unroll
    for (int p = 0; p < 4; p++) {
        int row = wn + (p << 4) + ((lane >> 4) << 3) + (lane & 7);
        b_byte[p] = (unsigned)(A_BYTES + row * 128);
        b_r7[p] = row & 7;
    }

    // prologue: stage chunks 0, 1
#pragma unroll
    for (int pc = 0; pc < 2; pc++) {
        unsigned sb = sbase + pc * STAGE_BYTES;
#pragma unroll
        for (int p = 0; p < 8; p++) cp16(sb + aso[p], agp[p] + pc * CKH);
#pragma unroll
        for (int p = 0; p < 8; p++) cp16(sb + bso[p], bgp[p] + pc * CKH);
        asm volatile("cp.async.commit_group;" ::: "memory");
    }

#pragma unroll
    for (int ch = 0; ch < NCHUNK; ch++) {
        if (ch == NCHUNK - 1)
            asm volatile("cp.async.wait_group 0;" ::: "memory");
        else
            asm volatile("cp.async.wait_group 1;" ::: "memory");
        __syncthreads();

        if (ch + 2 < NCHUNK) {
            const int k0 = (ch + 2) * CKH;
            unsigned sb = sbase + (unsigned)(((ch + 2) % NSTAGE) * STAGE_BYTES);
#pragma unroll
            for (int p = 0; p < 8; p++) cp16(sb + aso[p], agp[p] + k0);
#pragma unroll
            for (int p = 0; p < 8; p++) cp16(sb + bso[p], bgp[p] + k0);
            asm volatile("cp.async.commit_group;" ::: "memory");
        }

        const unsigned stg = sbase + (unsigned)((ch % NSTAGE) * STAGE_BYTES);

#pragma unroll
        for (int s = 0; s < 4; s++) {
            unsigned a[4][4];
#pragma unroll
            for (int mf = 0; mf < 4; mf++) {
                unsigned ad = stg + a_byte[mf]
                    + (unsigned)(((((s << 1) | a_csel) ^ a_r7[mf])) << 4);
                LDSM4(a[mf][0], a[mf][1], a[mf][2], a[mf][3], ad);
            }
            unsigned b[8][2];
#pragma unroll
            for (int p = 0; p < 4; p++) {
                unsigned bd = stg + b_byte[p]
                    + (unsigned)(((((s << 1) | b_csel) ^ b_r7[p])) << 4);
                LDSM4(b[2 * p][0], b[2 * p][1], b[2 * p + 1][0], b[2 * p + 1][1], bd);
            }
#pragma unroll
            for (int nf = 0; nf < 8; nf++)
#pragma unroll
                for (int mf = 0; mf < 4; mf++)
                    mma_bf16(c[mf][nf], a[mf][0], a[mf][1], a[mf][2], a[mf][3],
                             b[nf][0], b[nf][1]);
        }
    }

    // epilogue: warp covers 64 N-cols = two j's
    const float invt = 1.0f / temp_p[0];
#pragma unroll
    for (int mf = 0; mf < 4; mf++) {
#pragma unroll
        for (int h = 0; h < 2; h++) {
#pragma unroll
            for (int jh = 0; jh < 2; jh++) {
                float v = -INFINITY;
#pragma unroll
                for (int nf = 4 * jh; nf < 4 * jh + 4; nf++)
                    v = fmaxf(v, fmaxf(c[mf][nf][2 * h], c[mf][nf][2 * h + 1]));
                v = fmaxf(v, __shfl_xor_sync(0xffffffffu, v, 1));
                v = fmaxf(v, __shfl_xor_sync(0xffffffffu, v, 2));
                if (tg == 0) {
                    int row = i0 + wm + (mf << 4) + (h << 3) + g;
                    int j   = ((jq0 + wn) >> 5) + jh;
                    g_simmax[(size_t)row * BB + j] = v * invt;
                }
            }
        }
    }
}

// ---------------------------------------------------------------------------
// Per-row loss: one warp per row; exact top-512 via 32-step binary search.
// Last finished block reduces g_rowloss to the scalar (deterministic order).
// ---------------------------------------------------------------------------
__device__ __forceinline__ unsigned f2key(float f)
{
    unsigned b = __float_as_uint(f);
    return (b & 0x80000000u) ? ~b : (b | 0x80000000u);
}
__device__ __forceinline__ float key2f(unsigned k)
{
    return __uint_as_float((k & 0x80000000u) ? (k ^ 0x80000000u) : ~k);
}

__global__ __launch_bounds__(128) void loss_warp(float* __restrict__ out)
{
    __shared__ float red[128];
    __shared__ bool s_last;

    const int lane = threadIdx.x & 31;
    const int i = (blockIdx.x << 2) + (threadIdx.x >> 5);
    const float* rowp = g_simmax + (size_t)i * BB;

    float v[32];
    float m = -INFINITY, posl = 0.f;
#pragma unroll
    for (int r = 0; r < 32; r++) {
        v[r] = rowp[(r << 5) + lane];
        m = fmaxf(m, v[r]);
        if ((r << 5) + lane == i) posl = v[r];
    }
#pragma unroll
    for (int s = 16; s >= 1; s >>= 1)
        m = fmaxf(m, __shfl_xor_sync(0xffffffffu, m, s));
    float pos = posl;
#pragma unroll
    for (int s = 16; s >= 1; s >>= 1)
        pos += __shfl_xor_sync(0xffffffffu, pos, s);

    float ev[32]; unsigned key[32];
    float sum = 0.f;
#pragma unroll
    for (int r = 0; r < 32; r++) {
        ev[r] = expf(v[r] - m);
        sum += ev[r];
        key[r] = ((r << 5) + lane == i) ? 0u : f2key(v[r]);
    }
#pragma unroll
    for (int s = 16; s >= 1; s >>= 1)
        sum += __shfl_xor_sync(0xffffffffu, sum, s);
    const float lse_all = logf(sum) + m;

    unsigned lo = 0u, hi = 0xFFFFFFFFu;
    for (int it = 0; it < 32; it++) {
        unsigned mid = lo + ((hi - lo) >> 1);
        unsigned cl = 0;
#pragma unroll
        for (int r = 0; r < 32; r++) cl += (key[r] > mid);
        unsigned cnt = __reduce_add_sync(0xffffffffu, cl);
        if (cnt >= NUM_HARD) lo = mid; else hi = mid;
    }

    unsigned cgl = 0; float hsum = 0.f;
#pragma unroll
    for (int r = 0; r < 32; r++) {
        if (key[r] > hi) { cgl++; hsum += ev[r]; }
    }
    unsigned cgt = __reduce_add_sync(0xffffffffu, cgl);
#pragma unroll
    for (int s = 16; s >= 1; s >>= 1)
        hsum += __shfl_xor_sync(0xffffffffu, hsum, s);
    hsum += (float)(NUM_HARD - cgt) * expf(key2f(hi) - m) + expf(pos - m);

    if (lane == 0) {
        const float lse_h = logf(hsum) + m;
        g_rowloss[i] = (lse_all - pos) + 0.5f * (lse_h - pos);
    }

    __syncthreads();
    if (threadIdx.x == 0) {
        __threadfence();
        unsigned prev = atomicAdd(&g_done, 1u);
        s_last = (prev == (BB / 4) - 1);
    }
    __syncthreads();
    if (s_last) {
        const int t = threadIdx.x;
        float s = 0.f;
#pragma unroll
        for (int p = 0; p < 8; p++) s += g_rowloss[t + p * 128];
        red[t] = s;
        __syncthreads();
        for (int st = 64; st > 0; st >>= 1) {
            if (t < st) red[t] += red[t + st];
            __syncthreads();
        }
        if (t == 0) out[0] = red[0] / (float)BB;
    }
}

extern "C" void kernel_launch(void* const* d_in, const int* in_sizes, int n_in,
                              void* d_out, int out_size)
{
    const float* fusion = (const float*)d_in[0];
    const float* target = (const float*)d_in[1];
    const float* temp   = (const float*)d_in[2];
    float* out = (float*)d_out;

    cudaFuncSetAttribute(sim_tc, cudaFuncAttributeMaxDynamicSharedMemorySize,
                         SMEM_BYTES);

    cvt_bf16_kernel<<<2048, 256>>>((const float4*)fusion, (const float4*)target);

    dim3 grid(BB / CTA_M, NJQ / CTA_N);   // (8, 256)
    sim_tc<<<grid, NTHR, SMEM_BYTES>>>(temp);

    loss_warp<<<BB / 4, 128>>>(out);
}

// round 17
// speedup vs baseline: 1.0981x; 1.0168x over previous
#include <cuda_runtime.h>
#include <cuda_bf16.h>
#include <math.h>
#include <stdint.h>

#define BB 1024
#define QQ 32
#define DD 512
#define NJQ (BB * QQ)
#define NUM_HARD 512

#define CTA_M 128
#define CTA_N 128
#define CKH   64                         // K halves per chunk (128 B/row)
#define NCHUNK (DD / CKH)                // 8
#define A_BYTES (CTA_M * CKH * 2)        // 16384
#define B_BYTES (CTA_N * CKH * 2)        // 16384
#define STAGE_BYTES (A_BYTES + B_BYTES)  // 32768
#define NSTAGE 3
#define SMEM_BYTES (NSTAGE * STAGE_BYTES) // 98304 -> 2 CTAs/SM
#define NTHR 128                          // 4 warps of 64x64

#define FN4 (BB * DD / 4)
#define TN4 (NJQ * DD / 4)

__device__ float g_simmax[BB * BB];
__device__ float g_rowloss[BB];
__device__ unsigned g_done;
__device__ uint4 g_fusion_h[BB * DD / 8];
__device__ uint4 g_target_h[NJQ * DD / 8];

// ---------------------------------------------------------------------------
// fp32 -> bf16 (RNE): 2 consecutive float4 in, 1 uint4 out per thread-iter
// (coalesced; the measured-good R13/R14/R16 version).
// ---------------------------------------------------------------------------
__device__ __forceinline__ unsigned pack_bf16(float x, float y)
{
    __nv_bfloat162 h = __float22bfloat162_rn(make_float2(x, y));
    return *(unsigned*)&h;
}

__global__ __launch_bounds__(256) void cvt_bf16_kernel(
    const float4* __restrict__ fus, const float4* __restrict__ tgt)
{
    if (blockIdx.x == 0 && threadIdx.x == 0) g_done = 0;
    const int nfo = FN4 / 2;
    const int nto = TN4 / 2;
    for (int i = blockIdx.x * blockDim.x + threadIdx.x; i < nfo + nto;
         i += gridDim.x * blockDim.x) {
        const float4* src;
        uint4* dst;
        if (i < nfo) { src = fus + 2 * (size_t)i;          dst = g_fusion_h + i; }
        else { int k = i - nfo; src = tgt + 2 * (size_t)k; dst = g_target_h + k; }
        float4 v0 = src[0];
        float4 v1 = src[1];
        uint4 o;
        o.x = pack_bf16(v0.x, v0.y);
        o.y = pack_bf16(v0.z, v0.w);
        o.z = pack_bf16(v1.x, v1.y);
        o.w = pack_bf16(v1.z, v1.w);
        *dst = o;
    }
}

// ---------------------------------------------------------------------------
// bf16 tensor-core GEMM + max-over-q epilogue (mma.m16n8k16, fp32 accum).
// CTA 128x128, 4 warps (2x2) of 64x64; 2 CTAs/SM; chunk loop fully unrolled.
// At the mma.sync hardware ceiling (~926 MAC/cyc/SM) — unchanged this round.
// ---------------------------------------------------------------------------
__device__ __forceinline__ void mma_bf16(float c[4], unsigned a0, unsigned a1,
                                         unsigned a2, unsigned a3,
                                         unsigned b0, unsigned b1)
{
    asm volatile(
        "mma.sync.aligned.m16n8k16.row.col.f32.bf16.bf16.f32 "
        "{%0,%1,%2,%3},{%4,%5,%6,%7},{%8,%9},{%0,%1,%2,%3};"
        : "+f"(c[0]), "+f"(c[1]), "+f"(c[2]), "+f"(c[3])
        : "r"(a0), "r"(a1), "r"(a2), "r"(a3), "r"(b0), "r"(b1));
}

#define LDSM4(r0, r1, r2, r3, addr) \
    asm volatile("ldmatrix.sync.aligned.m8n8.x4.shared.b16 {%0,%1,%2,%3}, [%4];" \
                 : "=r"(r0), "=r"(r1), "=r"(r2), "=r"(r3) : "r"(addr))

__device__ __forceinline__ void cp16(unsigned saddr, const void* gaddr)
{
    asm volatile("cp.async.cg.shared.global [%0], [%1], 16;"
                 :: "r"(saddr), "l"(gaddr));
}

__global__ __launch_bounds__(NTHR, 2) void sim_tc(const float* __restrict__ temp_p)
{
    extern __shared__ float sm[];
    const int t    = threadIdx.x;
    const int wid  = t >> 5;
    const int lane = t & 31;
    const int g    = lane >> 2;
    const int tg   = lane & 3;
    const int wm   = (wid >> 1) * 64;
    const int wn   = (wid & 1) * 64;
    const int i0   = blockIdx.x * CTA_M;
    const int jq0  = blockIdx.y * CTA_N;

    float c[4][8][4];
#pragma unroll
    for (int mf = 0; mf < 4; mf++)
#pragma unroll
        for (int nf = 0; nf < 8; nf++)
#pragma unroll
            for (int r = 0; r < 4; r++) c[mf][nf][r] = 0.f;

    const unsigned sbase = (unsigned)__cvta_generic_to_shared(sm);
    const __nv_bfloat16* fus = (const __nv_bfloat16*)g_fusion_h;
    const __nv_bfloat16* tgt = (const __nv_bfloat16*)g_target_h;

    const __nv_bfloat16* agp[8]; unsigned aso[8];
#pragma unroll
    for (int p = 0; p < 8; p++) {
        int idx4 = t + p * NTHR;
        int row = idx4 >> 3, kb = idx4 & 7;
        agp[p] = fus + (size_t)(i0 + row) * DD + kb * 8;
        aso[p] = (unsigned)(row * 128 + ((kb ^ (row & 7)) << 4));
    }
    const __nv_bfloat16* bgp[8]; unsigned bso[8];
#pragma unroll
    for (int p = 0; p < 8; p++) {
        int idx4 = t + p * NTHR;
        int row = idx4 >> 3, kb = idx4 & 7;
        bgp[p] = tgt + (size_t)(jq0 + row) * DD + kb * 8;
        bso[p] = (unsigned)(A_BYTES + row * 128 + ((kb ^ (row & 7)) << 4));
    }

    unsigned a_byte[4]; int a_r7[4];
    const int a_csel = lane >> 4;
#pragma unroll
    for (int mf = 0; mf < 4; mf++) {
        int row = wm + (mf << 4) + (((lane >> 3) & 1) << 3) + (lane & 7);
        a_byte[mf] = (unsigned)(row * 128);
        a_r7[mf] = row & 7;
    }
    unsigned b_byte[4]; int b_r7[4];
    const int b_csel = (lane >> 3) & 1;
#pragma unroll
    for (int p = 0; p < 4; p++) {
        int row = wn + (p << 4) + ((lane >> 4) << 3) + (lane & 7);
        b_byte[p] = (unsigned)(A_BYTES + row * 128);
        b_r7[p] = row & 7;
    }

    // prologue: stage chunks 0, 1
#pragma unroll
    for (int pc = 0; pc < 2; pc++) {
        unsigned sb = sbase + pc * STAGE_BYTES;
#pragma unroll
        for (int p = 0; p < 8; p++) cp16(sb + aso[p], agp[p] + pc * CKH);
#pragma unroll
        for (int p = 0; p < 8; p++) cp16(sb + bso[p], bgp[p] + pc * CKH);
        asm volatile("cp.async.commit_group;" ::: "memory");
    }

#pragma unroll
    for (int ch = 0; ch < NCHUNK; ch++) {
        if (ch == NCHUNK - 1)
            asm volatile("cp.async.wait_group 0;" ::: "memory");
        else
            asm volatile("cp.async.wait_group 1;" ::: "memory");
        __syncthreads();

        if (ch + 2 < NCHUNK) {
            const int k0 = (ch + 2) * CKH;
            unsigned sb = sbase + (unsigned)(((ch + 2) % NSTAGE) * STAGE_BYTES);
#pragma unroll
            for (int p = 0; p < 8; p++) cp16(sb + aso[p], agp[p] + k0);
#pragma unroll
            for (int p = 0; p < 8; p++) cp16(sb + bso[p], bgp[p] + k0);
            asm volatile("cp.async.commit_group;" ::: "memory");
        }

        const unsigned stg = sbase + (unsigned)((ch % NSTAGE) * STAGE_BYTES);

#pragma unroll
        for (int s = 0; s < 4; s++) {
            unsigned a[4][4];
#pragma unroll
            for (int mf = 0; mf < 4; mf++) {
                unsigned ad = stg + a_byte[mf]
                    + (unsigned)(((((s << 1) | a_csel) ^ a_r7[mf])) << 4);
                LDSM4(a[mf][0], a[mf][1], a[mf][2], a[mf][3], ad);
            }
            unsigned b[8][2];
#pragma unroll
            for (int p = 0; p < 4; p++) {
                unsigned bd = stg + b_byte[p]
                    + (unsigned)(((((s << 1) | b_csel) ^ b_r7[p])) << 4);
                LDSM4(b[2 * p][0], b[2 * p][1], b[2 * p + 1][0], b[2 * p + 1][1], bd);
            }
#pragma unroll
            for (int nf = 0; nf < 8; nf++)
#pragma unroll
                for (int mf = 0; mf < 4; mf++)
                    mma_bf16(c[mf][nf], a[mf][0], a[mf][1], a[mf][2], a[mf][3],
                             b[nf][0], b[nf][1]);
        }
    }

    // epilogue: warp covers 64 N-cols = two j's
    const float invt = 1.0f / temp_p[0];
#pragma unroll
    for (int mf = 0; mf < 4; mf++) {
#pragma unroll
        for (int h = 0; h < 2; h++) {
#pragma unroll
            for (int jh = 0; jh < 2; jh++) {
                float v = -INFINITY;
#pragma unroll
                for (int nf = 4 * jh; nf < 4 * jh + 4; nf++)
                    v = fmaxf(v, fmaxf(c[mf][nf][2 * h], c[mf][nf][2 * h + 1]));
                v = fmaxf(v, __shfl_xor_sync(0xffffffffu, v, 1));
                v = fmaxf(v, __shfl_xor_sync(0xffffffffu, v, 2));
                if (tg == 0) {
                    int row = i0 + wm + (mf << 4) + (h << 3) + g;
                    int j   = ((jq0 + wn) >> 5) + jh;
                    g_simmax[(size_t)row * BB + j] = v * invt;
                }
            }
        }
    }
}

// ---------------------------------------------------------------------------
// Per-row loss: one warp per row. Exact top-512 threshold via binary search
// over [kmin-1, kmax] (data-adaptive, invariant-safe for any data) with
// dynamic termination — ~22-25 iterations instead of fixed 32. REDUX-based
// max reduction. Last finished block reduces to the scalar (fixed order).
// ---------------------------------------------------------------------------
__device__ __forceinline__ unsigned f2key(float f)
{
    unsigned b = __float_as_uint(f);
    return (b & 0x80000000u) ? ~b : (b | 0x80000000u);
}
__device__ __forceinline__ float key2f(unsigned k)
{
    return __uint_as_float((k & 0x80000000u) ? (k ^ 0x80000000u) : ~k);
}

__global__ __launch_bounds__(128) void loss_warp(float* __restrict__ out)
{
    __shared__ float red[128];
    __shared__ bool s_last;

    const int lane = threadIdx.x & 31;
    const int i = (blockIdx.x << 2) + (threadIdx.x >> 5);
    const float* rowp = g_simmax + (size_t)i * BB;

    float v[32];
    unsigned key[32];
    unsigned kmaxl = 0u, kminl = 0xFFFFFFFFu;
    float posl = 0.f;
    unsigned allmaxl = 0u;
#pragma unroll
    for (int r = 0; r < 32; r++) {
        v[r] = rowp[(r << 5) + lane];
        unsigned kv = f2key(v[r]);
        allmaxl = (kv > allmaxl) ? kv : allmaxl;
        const bool diag = ((r << 5) + lane == i);
        if (diag) posl = v[r];
        key[r] = diag ? 0u : kv;
        if (!diag) {
            kmaxl = (kv > kmaxl) ? kv : kmaxl;
            kminl = (kv < kminl) ? kv : kminl;
        }
    }
    const float m = key2f(__reduce_max_sync(0xffffffffu, allmaxl));
    float pos = posl;
#pragma unroll
    for (int s = 16; s >= 1; s >>= 1)
        pos += __shfl_xor_sync(0xffffffffu, pos, s);

    float ev[32];
    float sum = 0.f;
#pragma unroll
    for (int r = 0; r < 32; r++) {
        ev[r] = expf(v[r] - m);
        sum += ev[r];
    }
#pragma unroll
    for (int s = 16; s >= 1; s >>= 1)
        sum += __shfl_xor_sync(0xffffffffu, sum, s);
    const float lse_all = logf(sum) + m;

    // adaptive bounds: lo = kmin-1 (cnt >= 512 trivially), hi = kmax (cnt == 0)
    unsigned lo = __reduce_min_sync(0xffffffffu, kminl) - 1u;
    unsigned hi = __reduce_max_sync(0xffffffffu, kmaxl);
    while (hi - lo > 1u) {
        unsigned mid = lo + ((hi - lo) >> 1);
        unsigned cl = 0;
#pragma unroll
        for (int r = 0; r < 32; r++) cl += (key[r] > mid);
        unsigned cnt = __reduce_add_sync(0xffffffffu, cl);
        if (cnt >= NUM_HARD) lo = mid; else hi = mid;
    }
    // hi == exact 512th-largest off-diagonal key

    unsigned cgl = 0; float hsum = 0.f;
#pragma unroll
    for (int r = 0; r < 32; r++) {
        if (key[r] > hi) { cgl++; hsum += ev[r]; }
    }
    unsigned cgt = __reduce_add_sync(0xffffffffu, cgl);
#pragma unroll
    for (int s = 16; s >= 1; s >>= 1)
        hsum += __shfl_xor_sync(0xffffffffu, hsum, s);
    hsum += (float)(NUM_HARD - cgt) * expf(key2f(hi) - m) + expf(pos - m);

    if (lane == 0) {
        const float lse_h = logf(hsum) + m;
        g_rowloss[i] = (lse_all - pos) + 0.5f * (lse_h - pos);
    }

    __syncthreads();
    if (threadIdx.x == 0) {
        __threadfence();
        unsigned prev = atomicAdd(&g_done, 1u);
        s_last = (prev == (BB / 4) - 1);
    }
    __syncthreads();
    if (s_last) {
        const int t = threadIdx.x;
        float s = 0.f;
#pragma unroll
        for (int p = 0; p < 8; p++) s += g_rowloss[t + p * 128];
        red[t] = s;
        __syncthreads();
        for (int st = 64; st > 0; st >>= 1) {
            if (t < st) red[t] += red[t + st];
            __syncthreads();
        }
        if (t == 0) out[0] = red[0] / (float)BB;
    }
}

extern "C" void kernel_launch(void* const* d_in, const int* in_sizes, int n_in,
                              void* d_out, int out_size)
{
    const float* fusion = (const float*)d_in[0];
    const float* target = (const float*)d_in[1];
    const float* temp   = (const float*)d_in[2];
    float* out = (float*)d_out;

    cudaFuncSetAttribute(sim_tc, cudaFuncAttributeMaxDynamicSharedMemorySize,
                         SMEM_BYTES);

    cvt_bf16_kernel<<<2048, 256>>>((const float4*)fusion, (const float4*)target);

    dim3 grid(BB / CTA_M, NJQ / CTA_N);   // (8, 256)
    sim_tc<<<grid, NTHR, SMEM_BYTES>>>(temp);

    loss_warp<<<BB / 4, 128>>>(out);
}